// round 1
// baseline (speedup 1.0000x reference)
#include <cuda_runtime.h>

#define NU 96
#define IMG 32
#define SHAPE (NU * IMG)          // 3072
#define NUNITS (NU * NU)          // 9216
#define NELEM (SHAPE * SHAPE)     // 9437184

// Scratch (no allocations allowed)
__device__ unsigned long long g_best;
__device__ float g_fm[NUNITS];
__device__ float g_va[NUNITS];

__global__ void k_reset() {
    g_best = 0xFFFFFFFFFFFFFFFFULL;
}

// One block per unit tile: z = sum over 32x32 of (som-x)^2/var, then
// atomicMin of (orderable_bits(z) << 32 | unit) -> first-index argmin.
__global__ void __launch_bounds__(256) k_z(const float* __restrict__ som,
                                           const float* __restrict__ var,
                                           const float* __restrict__ x) {
    int unit = blockIdx.x;
    int ui = unit / NU, uj = unit % NU;
    const float* sbase = som + (long)(ui * IMG) * SHAPE + uj * IMG;
    const float* vbase = var + (long)(ui * IMG) * SHAPE + uj * IMG;
    int t = threadIdx.x;

    float acc = 0.0f;
#pragma unroll
    for (int k = 0; k < 4; k++) {
        int p = t + k * 256;          // pixel index 0..1023
        int pi = p >> 5, pj = p & 31;
        float s  = sbase[pi * SHAPE + pj];
        float v  = vbase[pi * SHAPE + pj];
        float xi = x[p];              // x[pi*32+pj] == x[p]
        float d = s - xi;
        acc += d * d / v;
    }

    // warp reduce
#pragma unroll
    for (int o = 16; o; o >>= 1) acc += __shfl_down_sync(0xffffffffu, acc, o);
    __shared__ float ws[8];
    if ((t & 31) == 0) ws[t >> 5] = acc;
    __syncthreads();
    if (t < 8) {
        acc = ws[t];
#pragma unroll
        for (int o = 4; o; o >>= 1) acc += __shfl_down_sync(0xffu, acc, o);
        if (t == 0) {
            unsigned u = __float_as_uint(acc);
            u = (u & 0x80000000u) ? ~u : (u | 0x80000000u);  // orderable
            unsigned long long key = ((unsigned long long)u << 32) | (unsigned)unit;
            atomicMin(&g_best, key);
        }
    }
}

// Single block: derive BMU scalars, fill fm/va tables, write radius/lr outputs.
__global__ void __launch_bounds__(256) k_prep(const float* __restrict__ radius,
                                              const float* __restrict__ lr,
                                              const float* __restrict__ bmu_count,
                                              float* __restrict__ out_radius,
                                              float* __restrict__ out_lr) {
    __shared__ float s_bi, s_bj, s_r, s_dm, s_cst;
    __shared__ int s_bmu;
    if (threadIdx.x == 0) {
        int bmu = (int)(g_best & 0xFFFFFFFFULL);
        s_bmu = bmu;
        int bi = bmu / NU, bj = bmu % NU;
        s_bi = (float)bi;
        s_bj = (float)bj;
        float r   = radius[bmu];
        float lrb = lr[bmu];
        float dm  = 1.0f / (2.0f * r * r);
        s_r = r;
        s_dm = dm;
        s_cst = -logf(1e-7f / lrb) / dm;
    }
    __syncthreads();
    float bi = s_bi, bj = s_bj, r = s_r, dm = s_dm, cst = s_cst;
    int bmu = s_bmu;

    for (int e = threadIdx.x; e < NUNITS; e += blockDim.x) {
        int i = e / NU, j = e % NU;
        float di = (float)i - bi;
        float dj = (float)j - bj;
        float cart = sqrtf(di * di + dj * dj);
        float mod = (cart > r) ? 0.0f : cart;
        g_fm[e] = lr[e] * expf(-mod) * dm;
        float sig = 1.0f / (1.0f + expf(-cart / cst));
        float va = 0.9f - 0.5f + sig;          // ALPHA - 0.5 + sigmoid
        g_va[e] = fminf(fmaxf(va, 0.0f), 1.0f);

        float nr = (e == bmu) ? expf(-bmu_count[bmu * 10] / 15.0f) : radius[e];
        out_radius[e] = fmaxf(nr, 1e-5f);
        float nl = (e == bmu) ? expf(-bmu_count[bmu * 10] / 25.0f) : lr[e];
        out_lr[e] = fmaxf(nl, 1e-5f);
    }
}

// One block per unit tile: elementwise codebook + EMA variance update, float4.
__global__ void __launch_bounds__(256) k_update(const float* __restrict__ som,
                                                const float* __restrict__ var,
                                                const float* __restrict__ x,
                                                float* __restrict__ out_som,
                                                float* __restrict__ out_var) {
    int unit = blockIdx.x;
    int ui = unit / NU, uj = unit % NU;
    float fm = g_fm[unit];
    float va = g_va[unit];
    float ivb = 1.0f - va;

    int t = threadIdx.x;              // one float4 per thread (256 * 4 = 1024)
    int pi = t >> 3, pj4 = t & 7;     // row, float4-col within tile
    long off = (long)(ui * IMG + pi) * SHAPE + uj * IMG + pj4 * 4;

    float4 s  = *(const float4*)(som + off);
    float4 v  = *(const float4*)(var + off);
    float4 xv = *(const float4*)(x + pi * IMG + pj4 * 4);

    float4 os, ov;
    {
        float ns = s.x + fm * (xv.x - s.x);
        float d = xv.x - ns;
        ov.x = va * v.x + ivb * d * d;
        os.x = fminf(fmaxf(ns, 0.0f), 1.0f);
    }
    {
        float ns = s.y + fm * (xv.y - s.y);
        float d = xv.y - ns;
        ov.y = va * v.y + ivb * d * d;
        os.y = fminf(fmaxf(ns, 0.0f), 1.0f);
    }
    {
        float ns = s.z + fm * (xv.z - s.z);
        float d = xv.z - ns;
        ov.z = va * v.z + ivb * d * d;
        os.z = fminf(fmaxf(ns, 0.0f), 1.0f);
    }
    {
        float ns = s.w + fm * (xv.w - s.w);
        float d = xv.w - ns;
        ov.w = va * v.w + ivb * d * d;
        os.w = fminf(fmaxf(ns, 0.0f), 1.0f);
    }

    *(float4*)(out_som + off) = os;
    *(float4*)(out_var + off) = ov;
}

extern "C" void kernel_launch(void* const* d_in, const int* in_sizes, int n_in,
                              void* d_out, int out_size) {
    const float* x      = (const float*)d_in[0];
    const float* som    = (const float*)d_in[1];
    const float* var    = (const float*)d_in[2];
    const float* radius = (const float*)d_in[3];
    const float* lr     = (const float*)d_in[4];
    const float* bmu    = (const float*)d_in[5];

    float* out      = (float*)d_out;
    float* out_som  = out;
    float* out_var  = out + (long)NELEM;
    float* out_rad  = out + 2L * NELEM;
    float* out_lr   = out + 2L * NELEM + NUNITS;

    k_reset<<<1, 1>>>();
    k_z<<<NUNITS, 256>>>(som, var, x);
    k_prep<<<1, 256>>>(radius, lr, bmu, out_rad, out_lr);
    k_update<<<NUNITS, 256>>>(som, var, x, out_som, out_var);
}

// round 2
// speedup vs baseline: 1.8936x; 1.8936x over previous
#include <cuda_runtime.h>

#define NU 96
#define IMG 32
#define SHAPE (NU * IMG)          // 3072
#define NUNITS (NU * NU)          // 9216
#define NELEM (SHAPE * SHAPE)     // 9437184

// Scratch (no allocations allowed); stateless across replays.
__device__ float g_z[NUNITS];
__device__ float g_params[5];     // bi, bj, r, dm, constant

// One block per unit tile: z = sum over 32x32 of (som-x)^2/var -> g_z[unit].
__global__ void __launch_bounds__(256) k_z(const float* __restrict__ som,
                                           const float* __restrict__ var,
                                           const float* __restrict__ x) {
    int unit = blockIdx.x;
    int ui = unit / NU, uj = unit % NU;
    int t = threadIdx.x;
    int pi = t >> 3, pj4 = (t & 7) * 4;     // 256 threads * float4 = 1024 elems

    long off = (long)(ui * IMG + pi) * SHAPE + uj * IMG + pj4;
    float4 s  = *(const float4*)(som + off);
    float4 v  = *(const float4*)(var + off);
    float4 xv = *(const float4*)(x + pi * IMG + pj4);

    float dx = s.x - xv.x, dy = s.y - xv.y, dz = s.z - xv.z, dw = s.w - xv.w;
    float acc = __fdividef(dx * dx, v.x) + __fdividef(dy * dy, v.y)
              + __fdividef(dz * dz, v.z) + __fdividef(dw * dw, v.w);

#pragma unroll
    for (int o = 16; o; o >>= 1) acc += __shfl_down_sync(0xffffffffu, acc, o);
    __shared__ float ws[8];
    if ((t & 31) == 0) ws[t >> 5] = acc;
    __syncthreads();
    if (t < 8) {
        acc = ws[t];
#pragma unroll
        for (int o = 4; o; o >>= 1) acc += __shfl_down_sync(0xffu, acc, o);
        if (t == 0) g_z[unit] = acc;
    }
}

// One block: argmin over g_z (first-occurrence tie-break), BMU scalars,
// and the radius / learning-rate outputs.
__global__ void __launch_bounds__(1024) k_mid(const float* __restrict__ radius,
                                              const float* __restrict__ lr,
                                              const float* __restrict__ bmu_count,
                                              float* __restrict__ out_radius,
                                              float* __restrict__ out_lr) {
    int t = threadIdx.x;
    unsigned long long best = 0xFFFFFFFFFFFFFFFFULL;
#pragma unroll
    for (int k = 0; k < NUNITS / 1024; k++) {
        int e = t + k * 1024;
        unsigned u = __float_as_uint(g_z[e]);
        u = (u & 0x80000000u) ? ~u : (u | 0x80000000u);   // orderable float bits
        unsigned long long key = ((unsigned long long)u << 32) | (unsigned)e;
        best = min(best, key);
    }
#pragma unroll
    for (int o = 16; o; o >>= 1) {
        unsigned long long other = __shfl_down_sync(0xffffffffu, best, o);
        best = min(best, other);
    }
    __shared__ unsigned long long ws[32];
    __shared__ int s_bmu;
    __shared__ float s_nr, s_nl;
    if ((t & 31) == 0) ws[t >> 5] = best;
    __syncthreads();
    if (t < 32) {
        best = ws[t];
#pragma unroll
        for (int o = 16; o; o >>= 1) {
            unsigned long long other = __shfl_down_sync(0xffffffffu, best, o);
            best = min(best, other);
        }
        if (t == 0) {
            int bmu = (int)(best & 0xFFFFFFFFULL);
            s_bmu = bmu;
            float r   = radius[bmu];
            float lrb = lr[bmu];
            float dm  = 1.0f / (2.0f * r * r);
            g_params[0] = (float)(bmu / NU);
            g_params[1] = (float)(bmu % NU);
            g_params[2] = r;
            g_params[3] = dm;
            g_params[4] = -logf(1e-7f / lrb) / dm;
            float c = bmu_count[bmu * 10];
            s_nr = expf(-c / 15.0f);
            s_nl = expf(-c / 25.0f);
        }
    }
    __syncthreads();
    int bmu = s_bmu;
    float nr = s_nr, nl = s_nl;
#pragma unroll
    for (int k = 0; k < NUNITS / 1024; k++) {
        int e = t + k * 1024;
        out_radius[e] = fmaxf((e == bmu) ? nr : radius[e], 1e-5f);
        out_lr[e]     = fmaxf((e == bmu) ? nl : lr[e], 1e-5f);
    }
}

// One block per unit tile: fm/va computed in-block, then float4 elementwise
// codebook + EMA variance update.
__global__ void __launch_bounds__(256) k_update(const float* __restrict__ som,
                                                const float* __restrict__ var,
                                                const float* __restrict__ x,
                                                const float* __restrict__ lr,
                                                float* __restrict__ out_som,
                                                float* __restrict__ out_var) {
    int unit = blockIdx.x;
    int ui = unit / NU, uj = unit % NU;

    // Per-unit scalars (computed redundantly per thread; all loads L2-broadcast)
    float bi = g_params[0], bj = g_params[1];
    float r = g_params[2], dm = g_params[3], cst = g_params[4];
    float di = (float)ui - bi;
    float dj = (float)uj - bj;
    float cart = sqrtf(di * di + dj * dj);
    float mod = (cart > r) ? 0.0f : cart;
    float fm = lr[unit] * expf(-mod) * dm;
    float sig = 1.0f / (1.0f + expf(-cart / cst));
    float va = fminf(fmaxf(0.4f + sig, 0.0f), 1.0f);   // ALPHA-0.5 = 0.4
    float ivb = 1.0f - va;

    int t = threadIdx.x;
    int pi = t >> 3, pj4 = (t & 7) * 4;
    long off = (long)(ui * IMG + pi) * SHAPE + uj * IMG + pj4;

    float4 s  = *(const float4*)(som + off);
    float4 v  = *(const float4*)(var + off);
    float4 xv = *(const float4*)(x + pi * IMG + pj4);

    float4 os, ov;
    {
        float ns = s.x + fm * (xv.x - s.x);
        float d = xv.x - ns;
        ov.x = va * v.x + ivb * d * d;
        os.x = fminf(fmaxf(ns, 0.0f), 1.0f);
    }
    {
        float ns = s.y + fm * (xv.y - s.y);
        float d = xv.y - ns;
        ov.y = va * v.y + ivb * d * d;
        os.y = fminf(fmaxf(ns, 0.0f), 1.0f);
    }
    {
        float ns = s.z + fm * (xv.z - s.z);
        float d = xv.z - ns;
        ov.z = va * v.z + ivb * d * d;
        os.z = fminf(fmaxf(ns, 0.0f), 1.0f);
    }
    {
        float ns = s.w + fm * (xv.w - s.w);
        float d = xv.w - ns;
        ov.w = va * v.w + ivb * d * d;
        os.w = fminf(fmaxf(ns, 0.0f), 1.0f);
    }

    *(float4*)(out_som + off) = os;
    *(float4*)(out_var + off) = ov;
}

extern "C" void kernel_launch(void* const* d_in, const int* in_sizes, int n_in,
                              void* d_out, int out_size) {
    const float* x      = (const float*)d_in[0];
    const float* som    = (const float*)d_in[1];
    const float* var    = (const float*)d_in[2];
    const float* radius = (const float*)d_in[3];
    const float* lr     = (const float*)d_in[4];
    const float* bmu    = (const float*)d_in[5];

    float* out      = (float*)d_out;
    float* out_som  = out;
    float* out_var  = out + (long)NELEM;
    float* out_rad  = out + 2L * NELEM;
    float* out_lr   = out + 2L * NELEM + NUNITS;

    k_z<<<NUNITS, 256>>>(som, var, x);
    k_mid<<<1, 1024>>>(radius, lr, bmu, out_rad, out_lr);
    k_update<<<NUNITS, 256>>>(som, var, x, lr, out_som, out_var);
}

// round 3
// speedup vs baseline: 1.9128x; 1.0101x over previous
#include <cuda_runtime.h>

#define NU 96
#define IMG 32
#define SHAPE 3072                 // NU*IMG
#define NUNITS 9216                // NU*NU
#define NELEM (SHAPE * SHAPE)
#define GRID 144
#define NTHREADS 1024
#define NWARPS (NTHREADS / 32)     // 32
#define TOTWARPS (GRID * NWARPS)   // 4608 -> exactly 2 tiles per warp

// Scratch (no allocations). Counters start 0 (static init) and are reset to 0
// by the last-exiting block every launch -> stateless across graph replays.
__device__ unsigned long long g_bmin[GRID];
__device__ unsigned g_arrive;
__device__ unsigned g_done;

__global__ void __launch_bounds__(NTHREADS) k_fused(
    const float* __restrict__ som, const float* __restrict__ var,
    const float* __restrict__ x, const float* __restrict__ radius,
    const float* __restrict__ lr, const float* __restrict__ bmu_count,
    float* __restrict__ out_som, float* __restrict__ out_var,
    float* __restrict__ out_rad, float* __restrict__ out_lr)
{
    __shared__ float4 sx[256];                 // x as 256 float4
    __shared__ unsigned long long swmin[NWARPS];
    __shared__ unsigned long long sbm[GRID];
    __shared__ float sp[5];                    // bi, bj, r, dm, cst
    __shared__ int  sbmu;

    const int t = threadIdx.x;
    const int lane = t & 31, warp = t >> 5;
    if (t < 256) sx[t] = ((const float4*)x)[t];
    __syncthreads();

    const int subrow = lane >> 3;              // 0..3
    const int col4   = lane & 7;               // float4 column 0..7
    const int gw = blockIdx.x * NWARPS + warp; // global warp id

    // ---------------- Phase 1: per-tile z + block-local argmin key ----------
    unsigned long long best = 0xFFFFFFFFFFFFFFFFULL;
#pragma unroll
    for (int it = 0; it < 2; it++) {
        int unit = gw + it * TOTWARPS;         // exactly 2 per warp
        int ui = unit / NU, uj = unit - ui * NU;
        const float* sb = som + (size_t)ui * IMG * SHAPE + uj * IMG;
        const float* vb = var + (size_t)ui * IMG * SHAPE + uj * IMG;

        float acc = 0.0f;
#pragma unroll
        for (int g = 0; g < 8; g++) {
            int rr = g * 4 + subrow;
            size_t o = (size_t)rr * SHAPE + col4 * 4;
            float4 s  = *(const float4*)(sb + o);
            float4 v  = *(const float4*)(vb + o);
            float4 xq = sx[rr * 8 + col4];
            float dx = s.x - xq.x, dy = s.y - xq.y;
            float dz = s.z - xq.z, dw = s.w - xq.w;
            acc += __fdividef(dx * dx, v.x) + __fdividef(dy * dy, v.y)
                 + __fdividef(dz * dz, v.z) + __fdividef(dw * dw, v.w);
        }
#pragma unroll
        for (int o = 16; o; o >>= 1) acc += __shfl_down_sync(0xffffffffu, acc, o);
        if (lane == 0) {
            unsigned u = __float_as_uint(acc);
            u = (u & 0x80000000u) ? ~u : (u | 0x80000000u);   // orderable bits
            unsigned long long key =
                ((unsigned long long)u << 32) | (unsigned)unit;
            if (key < best) best = key;
        }
    }
    if (lane == 0) swmin[warp] = best;
    __syncthreads();

    // ---------------- Grid barrier (all 144 blocks co-resident) -------------
    if (t == 0) {
        unsigned long long b = swmin[0];
#pragma unroll
        for (int i = 1; i < NWARPS; i++) if (swmin[i] < b) b = swmin[i];
        g_bmin[blockIdx.x] = b;
        __threadfence();
        atomicAdd(&g_arrive, 1u);
        while (*(volatile unsigned*)&g_arrive < GRID) { }
    }
    __syncthreads();
    __threadfence();

    // ---------------- Mid: global argmin + BMU scalars (per block) ----------
    if (t < GRID) sbm[t] = g_bmin[t];
    __syncthreads();
    if (t == 0) {
        unsigned long long b = sbm[0];
        for (int i = 1; i < GRID; i++) if (sbm[i] < b) b = sbm[i];
        int bmu = (int)(b & 0xFFFFFFFFULL);
        float r   = radius[bmu];
        float lrb = lr[bmu];
        float dm  = 1.0f / (2.0f * r * r);
        sp[0] = (float)(bmu / NU);
        sp[1] = (float)(bmu % NU);
        sp[2] = r;
        sp[3] = dm;
        sp[4] = -logf(1e-7f / lrb) / dm;
        sbmu = bmu;
    }
    __syncthreads();
    const float bi = sp[0], bj = sp[1], r = sp[2], dm = sp[3], cst = sp[4];
    const int bmu = sbmu;

    // Block 0: radius / learning-rate outputs (tiny)
    if (blockIdx.x == 0) {
        float c  = bmu_count[bmu * 10];
        float nr = expf(-c / 15.0f);
        float nl = expf(-c / 25.0f);
#pragma unroll
        for (int k = 0; k < NUNITS / NTHREADS; k++) {
            int e = t + k * NTHREADS;
            out_rad[e] = fmaxf((e == bmu) ? nr : radius[e], 1e-5f);
            out_lr[e]  = fmaxf((e == bmu) ? nl : lr[e], 1e-5f);
        }
    }

    // ---------------- Phase 2: codebook + EMA variance update ---------------
#pragma unroll
    for (int it = 0; it < 2; it++) {
        int unit = gw + it * TOTWARPS;
        int ui = unit / NU, uj = unit - ui * NU;

        float fm = 0.0f, va = 0.0f;
        if (lane == 0) {
            float di = (float)ui - bi;
            float dj = (float)uj - bj;
            float cart = sqrtf(di * di + dj * dj);
            float mod = (cart > r) ? 0.0f : cart;
            fm = lr[unit] * expf(-mod) * dm;
            float sig = 1.0f / (1.0f + expf(-cart / cst));
            va = fminf(fmaxf(0.4f + sig, 0.0f), 1.0f);   // ALPHA-0.5 = 0.4
        }
        fm = __shfl_sync(0xffffffffu, fm, 0);
        va = __shfl_sync(0xffffffffu, va, 0);
        float iva = 1.0f - va;

        size_t base = (size_t)ui * IMG * SHAPE + uj * IMG;
        const float* sb = som + base;
        const float* vb = var + base;
        float* osb = out_som + base;
        float* ovb = out_var + base;

#pragma unroll
        for (int g = 0; g < 8; g++) {
            int rr = g * 4 + subrow;
            size_t o = (size_t)rr * SHAPE + col4 * 4;
            float4 s  = *(const float4*)(sb + o);
            float4 v  = *(const float4*)(vb + o);
            float4 xq = sx[rr * 8 + col4];
            float4 os, ov;
            {
                float ns = s.x + fm * (xq.x - s.x);
                float d = xq.x - ns;
                ov.x = va * v.x + iva * d * d;
                os.x = fminf(fmaxf(ns, 0.0f), 1.0f);
            }
            {
                float ns = s.y + fm * (xq.y - s.y);
                float d = xq.y - ns;
                ov.y = va * v.y + iva * d * d;
                os.y = fminf(fmaxf(ns, 0.0f), 1.0f);
            }
            {
                float ns = s.z + fm * (xq.z - s.z);
                float d = xq.z - ns;
                ov.z = va * v.z + iva * d * d;
                os.z = fminf(fmaxf(ns, 0.0f), 1.0f);
            }
            {
                float ns = s.w + fm * (xq.w - s.w);
                float d = xq.w - ns;
                ov.w = va * v.w + iva * d * d;
                os.w = fminf(fmaxf(ns, 0.0f), 1.0f);
            }
            *(float4*)(osb + o) = os;
            *(float4*)(ovb + o) = ov;
        }
    }

    // ---------------- Exit: reset counters for next graph replay ------------
    __syncthreads();
    if (t == 0) {
        __threadfence();
        unsigned old = atomicAdd(&g_done, 1u);
        if (old == GRID - 1) {
            g_arrive = 0;
            g_done = 0;
            __threadfence();
        }
    }
}

extern "C" void kernel_launch(void* const* d_in, const int* in_sizes, int n_in,
                              void* d_out, int out_size) {
    const float* x      = (const float*)d_in[0];
    const float* som    = (const float*)d_in[1];
    const float* var    = (const float*)d_in[2];
    const float* radius = (const float*)d_in[3];
    const float* lr     = (const float*)d_in[4];
    const float* bmu    = (const float*)d_in[5];

    float* out      = (float*)d_out;
    float* out_som  = out;
    float* out_var  = out + (size_t)NELEM;
    float* out_rad  = out + 2ULL * NELEM;
    float* out_lr   = out + 2ULL * NELEM + NUNITS;

    k_fused<<<GRID, NTHREADS>>>(som, var, x, radius, lr, bmu,
                                out_som, out_var, out_rad, out_lr);
}

// round 6
// speedup vs baseline: 2.2065x; 1.1535x over previous
#include <cuda_runtime.h>

#define NU 96
#define IMG 32
#define SHAPE 3072                 // NU*IMG
#define NUNITS 9216                // NU*NU
#define NELEM (SHAPE * SHAPE)

// Scratch (no allocations); stateless across graph replays.
__device__ float g_z[NUNITS];
__device__ float g_params[5];      // bi, bj, r, dm, constant

// ---------------------------------------------------------------------------
// k_z: one 128-thread block per tile. Each thread: 2 rows (r, r+16), one
// float4 column -> 4 front-batched LDG.128 (high MLP), then 8 fast-divides.
// ---------------------------------------------------------------------------
__global__ void __launch_bounds__(128) k_z(const float* __restrict__ som,
                                           const float* __restrict__ var,
                                           const float* __restrict__ x) {
    const int unit = blockIdx.x;
    const int ui = unit / NU, uj = unit - ui * NU;
    const int t = threadIdx.x;
    const int rowA = t >> 3;              // 0..15
    const int col  = (t & 7) * 4;         // float4 column

    const float* sb = som + (size_t)ui * IMG * SHAPE + uj * IMG;
    const float* vb = var + (size_t)ui * IMG * SHAPE + uj * IMG;

    const size_t oA = (size_t)rowA * SHAPE + col;
    const size_t oB = (size_t)(rowA + 16) * SHAPE + col;

    // 4 independent loads batched up front
    float4 s0 = *(const float4*)(sb + oA);
    float4 s1 = *(const float4*)(sb + oB);
    float4 v0 = *(const float4*)(vb + oA);
    float4 v1 = *(const float4*)(vb + oB);
    float4 x0 = *(const float4*)(x + rowA * IMG + col);
    float4 x1 = *(const float4*)(x + (rowA + 16) * IMG + col);

    float d;
    float acc = 0.0f;
    d = s0.x - x0.x; acc += __fdividef(d * d, v0.x);
    d = s0.y - x0.y; acc += __fdividef(d * d, v0.y);
    d = s0.z - x0.z; acc += __fdividef(d * d, v0.z);
    d = s0.w - x0.w; acc += __fdividef(d * d, v0.w);
    d = s1.x - x1.x; acc += __fdividef(d * d, v1.x);
    d = s1.y - x1.y; acc += __fdividef(d * d, v1.y);
    d = s1.z - x1.z; acc += __fdividef(d * d, v1.z);
    d = s1.w - x1.w; acc += __fdividef(d * d, v1.w);

#pragma unroll
    for (int o = 16; o; o >>= 1) acc += __shfl_down_sync(0xffffffffu, acc, o);
    __shared__ float ws[4];
    if ((t & 31) == 0) ws[t >> 5] = acc;
    __syncthreads();
    if (t == 0)
        g_z[unit] = ws[0] + ws[1] + ws[2] + ws[3];
}

// ---------------------------------------------------------------------------
// k_mid: one block. Argmin over g_z (first-occurrence tie-break), BMU scalars,
// radius / learning-rate outputs.
// ---------------------------------------------------------------------------
__global__ void __launch_bounds__(1024) k_mid(const float* __restrict__ radius,
                                              const float* __restrict__ lr,
                                              const float* __restrict__ bmu_count,
                                              float* __restrict__ out_radius,
                                              float* __restrict__ out_lr) {
    const int t = threadIdx.x;
    unsigned long long best = 0xFFFFFFFFFFFFFFFFULL;
#pragma unroll
    for (int k = 0; k < NUNITS / 1024; k++) {
        int e = t + k * 1024;
        unsigned u = __float_as_uint(g_z[e]);
        u = (u & 0x80000000u) ? ~u : (u | 0x80000000u);   // orderable bits
        unsigned long long key = ((unsigned long long)u << 32) | (unsigned)e;
        best = min(best, key);
    }
#pragma unroll
    for (int o = 16; o; o >>= 1)
        best = min(best, __shfl_down_sync(0xffffffffu, best, o));
    __shared__ unsigned long long ws[32];
    __shared__ int s_bmu;
    __shared__ float s_nr, s_nl;
    if ((t & 31) == 0) ws[t >> 5] = best;
    __syncthreads();
    if (t < 32) {
        best = ws[t];
#pragma unroll
        for (int o = 16; o; o >>= 1)
            best = min(best, __shfl_down_sync(0xffffffffu, best, o));
        if (t == 0) {
            int bmu = (int)(best & 0xFFFFFFFFULL);
            s_bmu = bmu;
            float r   = radius[bmu];
            float lrb = lr[bmu];
            float dm  = 1.0f / (2.0f * r * r);
            g_params[0] = (float)(bmu / NU);
            g_params[1] = (float)(bmu % NU);
            g_params[2] = r;
            g_params[3] = dm;
            g_params[4] = -logf(1e-7f / lrb) / dm;
            float c = bmu_count[bmu * 10];
            s_nr = expf(-c / 15.0f);
            s_nl = expf(-c / 25.0f);
        }
    }
    __syncthreads();
    const int bmu = s_bmu;
    const float nr = s_nr, nl = s_nl;
#pragma unroll
    for (int k = 0; k < NUNITS / 1024; k++) {
        int e = t + k * 1024;
        out_radius[e] = fmaxf((e == bmu) ? nr : radius[e], 1e-5f);
        out_lr[e]     = fmaxf((e == bmu) ? nl : lr[e], 1e-5f);
    }
}

// ---------------------------------------------------------------------------
// k_update: one 128-thread block per tile. Reads som/var with last-use hint
// (they're L2-resident from k_z), writes outputs streaming (evict-first) so
// they don't evict the read data.
// ---------------------------------------------------------------------------
__global__ void __launch_bounds__(128) k_update(const float* __restrict__ som,
                                                const float* __restrict__ var,
                                                const float* __restrict__ x,
                                                const float* __restrict__ lr,
                                                float* __restrict__ out_som,
                                                float* __restrict__ out_var) {
    const int unit = blockIdx.x;
    const int ui = unit / NU, uj = unit - ui * NU;

    // Per-unit scalars (redundant per thread; scalar loads broadcast)
    const float bi = g_params[0], bj = g_params[1];
    const float r = g_params[2], dm = g_params[3], cst = g_params[4];
    const float di = (float)ui - bi;
    const float dj = (float)uj - bj;
    const float cart = sqrtf(di * di + dj * dj);
    const float mod = (cart > r) ? 0.0f : cart;
    const float fm = lr[unit] * expf(-mod) * dm;
    const float sig = 1.0f / (1.0f + expf(-cart / cst));
    const float va = fminf(fmaxf(0.4f + sig, 0.0f), 1.0f);  // ALPHA-0.5 = 0.4
    const float iva = 1.0f - va;

    const int t = threadIdx.x;
    const int rowA = t >> 3;
    const int col  = (t & 7) * 4;

    const size_t base = (size_t)ui * IMG * SHAPE + uj * IMG;
    const size_t oA = base + (size_t)rowA * SHAPE + col;
    const size_t oB = base + (size_t)(rowA + 16) * SHAPE + col;

    float4 s0 = __ldlu((const float4*)(som + oA));
    float4 s1 = __ldlu((const float4*)(som + oB));
    float4 v0 = __ldlu((const float4*)(var + oA));
    float4 v1 = __ldlu((const float4*)(var + oB));
    float4 x0 = *(const float4*)(x + rowA * IMG + col);
    float4 x1 = *(const float4*)(x + (rowA + 16) * IMG + col);

    float4 os0, ov0, os1, ov1;
#define UPD(S, X, OS, OV, V)                                   \
    {                                                          \
        float ns = S + fm * (X - S);                           \
        float dd = X - ns;                                     \
        OV = va * V + iva * dd * dd;                           \
        OS = fminf(fmaxf(ns, 0.0f), 1.0f);                     \
    }
    UPD(s0.x, x0.x, os0.x, ov0.x, v0.x)
    UPD(s0.y, x0.y, os0.y, ov0.y, v0.y)
    UPD(s0.z, x0.z, os0.z, ov0.z, v0.z)
    UPD(s0.w, x0.w, os0.w, ov0.w, v0.w)
    UPD(s1.x, x1.x, os1.x, ov1.x, v1.x)
    UPD(s1.y, x1.y, os1.y, ov1.y, v1.y)
    UPD(s1.z, x1.z, os1.z, ov1.z, v1.z)
    UPD(s1.w, x1.w, os1.w, ov1.w, v1.w)
#undef UPD

    __stcs((float4*)(out_som + oA), os0);
    __stcs((float4*)(out_som + oB), os1);
    __stcs((float4*)(out_var + oA), ov0);
    __stcs((float4*)(out_var + oB), ov1);
}

extern "C" void kernel_launch(void* const* d_in, const int* in_sizes, int n_in,
                              void* d_out, int out_size) {
    const float* x      = (const float*)d_in[0];
    const float* som    = (const float*)d_in[1];
    const float* var    = (const float*)d_in[2];
    const float* radius = (const float*)d_in[3];
    const float* lr     = (const float*)d_in[4];
    const float* bmu    = (const float*)d_in[5];

    float* out      = (float*)d_out;
    float* out_som  = out;
    float* out_var  = out + (size_t)NELEM;
    float* out_rad  = out + 2ULL * NELEM;
    float* out_lr   = out + 2ULL * NELEM + NUNITS;

    k_z<<<NUNITS, 128>>>(som, var, x);
    k_mid<<<1, 1024>>>(radius, lr, bmu, out_rad, out_lr);
    k_update<<<NUNITS, 128>>>(som, var, x, lr, out_som, out_var);
}

// round 7
// speedup vs baseline: 2.2083x; 1.0008x over previous
#include <cuda_runtime.h>

#define NU 96
#define IMG 32
#define SHAPE 3072                 // NU*IMG
#define NUNITS 9216                // NU*NU
#define NELEM (SHAPE * SHAPE)

// Scratch (no allocations); stateless across graph replays (g_count is
// reset to 0 by the last-finishing block of every launch).
__device__ float g_z[NUNITS];
__device__ float g_params[5];      // bi, bj, r, dm, constant
__device__ int   g_bmu;
__device__ unsigned g_count;       // zero-initialized, reset each launch

// ---------------------------------------------------------------------------
// k_z: one 128-thread block per tile (2 rows per thread, float4 columns,
// 4 front-batched LDG.128). Last finishing block does the global argmin and
// BMU scalar computation in-kernel (replaces the former k_mid launch).
// ---------------------------------------------------------------------------
__global__ void __launch_bounds__(128) k_z(const float* __restrict__ som,
                                           const float* __restrict__ var,
                                           const float* __restrict__ x,
                                           const float* __restrict__ radius,
                                           const float* __restrict__ lr) {
    const int unit = blockIdx.x;
    const int ui = unit / NU, uj = unit - ui * NU;
    const int t = threadIdx.x;
    const int rowA = t >> 3;              // 0..15
    const int col  = (t & 7) * 4;         // float4 column

    const float* sb = som + (size_t)ui * IMG * SHAPE + uj * IMG;
    const float* vb = var + (size_t)ui * IMG * SHAPE + uj * IMG;

    const size_t oA = (size_t)rowA * SHAPE + col;
    const size_t oB = (size_t)(rowA + 16) * SHAPE + col;

    float4 s0 = *(const float4*)(sb + oA);
    float4 s1 = *(const float4*)(sb + oB);
    float4 v0 = *(const float4*)(vb + oA);
    float4 v1 = *(const float4*)(vb + oB);
    float4 x0 = *(const float4*)(x + rowA * IMG + col);
    float4 x1 = *(const float4*)(x + (rowA + 16) * IMG + col);

    float d;
    float acc = 0.0f;
    d = s0.x - x0.x; acc += __fdividef(d * d, v0.x);
    d = s0.y - x0.y; acc += __fdividef(d * d, v0.y);
    d = s0.z - x0.z; acc += __fdividef(d * d, v0.z);
    d = s0.w - x0.w; acc += __fdividef(d * d, v0.w);
    d = s1.x - x1.x; acc += __fdividef(d * d, v1.x);
    d = s1.y - x1.y; acc += __fdividef(d * d, v1.y);
    d = s1.z - x1.z; acc += __fdividef(d * d, v1.z);
    d = s1.w - x1.w; acc += __fdividef(d * d, v1.w);

#pragma unroll
    for (int o = 16; o; o >>= 1) acc += __shfl_down_sync(0xffffffffu, acc, o);
    __shared__ float ws[4];
    if ((t & 31) == 0) ws[t >> 5] = acc;
    __syncthreads();
    if (t == 0)
        g_z[unit] = ws[0] + ws[1] + ws[2] + ws[3];

    // ---- last-block-done: global argmin + BMU scalars (replaces k_mid) ----
    __shared__ bool amLast;
    if (t == 0) {
        __threadfence();
        unsigned old = atomicAdd(&g_count, 1u);
        amLast = (old == NUNITS - 1);
    }
    __syncthreads();
    if (!amLast) return;
    __threadfence();                        // make all g_z writes visible

    unsigned long long best = 0xFFFFFFFFFFFFFFFFULL;
#pragma unroll
    for (int k = 0; k < NUNITS / 128; k++) {
        int e = t + k * 128;
        unsigned u = __float_as_uint(g_z[e]);
        u = (u & 0x80000000u) ? ~u : (u | 0x80000000u);   // orderable bits
        unsigned long long key = ((unsigned long long)u << 32) | (unsigned)e;
        best = min(best, key);
    }
#pragma unroll
    for (int o = 16; o; o >>= 1)
        best = min(best, __shfl_down_sync(0xffffffffu, best, o));
    __shared__ unsigned long long wm[4];
    if ((t & 31) == 0) wm[t >> 5] = best;
    __syncthreads();
    if (t == 0) {
        best = min(min(wm[0], wm[1]), min(wm[2], wm[3]));
        int bmu = (int)(best & 0xFFFFFFFFULL);
        float r   = radius[bmu];
        float lrb = lr[bmu];
        float dm  = 1.0f / (2.0f * r * r);
        g_params[0] = (float)(bmu / NU);
        g_params[1] = (float)(bmu % NU);
        g_params[2] = r;
        g_params[3] = dm;
        g_params[4] = -logf(1e-7f / lrb) / dm;
        g_bmu = bmu;
        g_count = 0;                        // reset for next graph replay
        __threadfence();
    }
}

// ---------------------------------------------------------------------------
// k_update: one 128-thread block per tile. som/var re-read with last-use hint
// (L2-resident from k_z), outputs written streaming. Blocks 0..71 also emit
// the radius / learning-rate outputs (128 entries each) in parallel.
// ---------------------------------------------------------------------------
__global__ void __launch_bounds__(128) k_update(const float* __restrict__ som,
                                                const float* __restrict__ var,
                                                const float* __restrict__ x,
                                                const float* __restrict__ lr,
                                                const float* __restrict__ radius,
                                                const float* __restrict__ bmu_count,
                                                float* __restrict__ out_som,
                                                float* __restrict__ out_var,
                                                float* __restrict__ out_rad,
                                                float* __restrict__ out_lr) {
    const int unit = blockIdx.x;
    const int ui = unit / NU, uj = unit - ui * NU;
    const int t = threadIdx.x;

    const float bi = g_params[0], bj = g_params[1];
    const float r = g_params[2], dm = g_params[3], cst = g_params[4];
    const int bmu = g_bmu;

    // Small side job: radius / learning-rate outputs (blocks 0..71)
    if (blockIdx.x < NUNITS / 128) {
        int e = blockIdx.x * 128 + t;
        float c  = bmu_count[bmu * 10];
        float nr = expf(-c / 15.0f);
        float nl = expf(-c / 25.0f);
        out_rad[e] = fmaxf((e == bmu) ? nr : radius[e], 1e-5f);
        out_lr[e]  = fmaxf((e == bmu) ? nl : lr[e], 1e-5f);
    }

    const float di = (float)ui - bi;
    const float dj = (float)uj - bj;
    const float cart = sqrtf(di * di + dj * dj);
    const float mod = (cart > r) ? 0.0f : cart;
    const float fm = lr[unit] * expf(-mod) * dm;
    const float sig = 1.0f / (1.0f + expf(-cart / cst));
    const float va = fminf(fmaxf(0.4f + sig, 0.0f), 1.0f);  // ALPHA-0.5 = 0.4
    const float iva = 1.0f - va;

    const int rowA = t >> 3;
    const int col  = (t & 7) * 4;

    const size_t base = (size_t)ui * IMG * SHAPE + uj * IMG;
    const size_t oA = base + (size_t)rowA * SHAPE + col;
    const size_t oB = base + (size_t)(rowA + 16) * SHAPE + col;

    float4 s0 = __ldlu((const float4*)(som + oA));
    float4 s1 = __ldlu((const float4*)(som + oB));
    float4 v0 = __ldlu((const float4*)(var + oA));
    float4 v1 = __ldlu((const float4*)(var + oB));
    float4 x0 = *(const float4*)(x + rowA * IMG + col);
    float4 x1 = *(const float4*)(x + (rowA + 16) * IMG + col);

    float4 os0, ov0, os1, ov1;
#define UPD(S, X, OS, OV, V)                                   \
    {                                                          \
        float ns = S + fm * (X - S);                           \
        float dd = X - ns;                                     \
        OV = va * V + iva * dd * dd;                           \
        OS = fminf(fmaxf(ns, 0.0f), 1.0f);                     \
    }
    UPD(s0.x, x0.x, os0.x, ov0.x, v0.x)
    UPD(s0.y, x0.y, os0.y, ov0.y, v0.y)
    UPD(s0.z, x0.z, os0.z, ov0.z, v0.z)
    UPD(s0.w, x0.w, os0.w, ov0.w, v0.w)
    UPD(s1.x, x1.x, os1.x, ov1.x, v1.x)
    UPD(s1.y, x1.y, os1.y, ov1.y, v1.y)
    UPD(s1.z, x1.z, os1.z, ov1.z, v1.z)
    UPD(s1.w, x1.w, os1.w, ov1.w, v1.w)
#undef UPD

    __stcs((float4*)(out_som + oA), os0);
    __stcs((float4*)(out_som + oB), os1);
    __stcs((float4*)(out_var + oA), ov0);
    __stcs((float4*)(out_var + oB), ov1);
}

extern "C" void kernel_launch(void* const* d_in, const int* in_sizes, int n_in,
                              void* d_out, int out_size) {
    const float* x      = (const float*)d_in[0];
    const float* som    = (const float*)d_in[1];
    const float* var    = (const float*)d_in[2];
    const float* radius = (const float*)d_in[3];
    const float* lr     = (const float*)d_in[4];
    const float* bmu    = (const float*)d_in[5];

    float* out      = (float*)d_out;
    float* out_som  = out;
    float* out_var  = out + (size_t)NELEM;
    float* out_rad  = out + 2ULL * NELEM;
    float* out_lr   = out + 2ULL * NELEM + NUNITS;

    k_z<<<NUNITS, 128>>>(som, var, x, radius, lr);
    k_update<<<NUNITS, 128>>>(som, var, x, lr, radius, bmu,
                              out_som, out_var, out_rad, out_lr);
}

// round 9
// speedup vs baseline: 2.2998x; 1.0414x over previous
#include <cuda_runtime.h>

#define NU 96
#define IMG 32
#define SHAPE 3072                 // NU*IMG
#define NUNITS 9216                // NU*NU
#define NELEM (SHAPE * SHAPE)
#define NBLK (NUNITS / 2)          // 4608 blocks, 2 tiles each

// Scratch (no allocations); stateless across graph replays (g_count reset by
// the last-finishing block each launch).
__device__ float g_z[NUNITS];
__device__ float g_params[5];      // bi, bj, r, dm, constant
__device__ int   g_bmu;
__device__ unsigned g_count;

// ---------------------------------------------------------------------------
// k_z: one 128-thread block per PAIR of adjacent tiles (same rows, adjacent
// uj). 8 front-batched LDG.128 per thread. Last block does the global argmin.
// ---------------------------------------------------------------------------
__global__ void __launch_bounds__(128) k_z(const float* __restrict__ som,
                                           const float* __restrict__ var,
                                           const float* __restrict__ x,
                                           const float* __restrict__ radius,
                                           const float* __restrict__ lr) {
    const int u0 = blockIdx.x * 2;        // even unit; u1 = u0+1 same ui
    const int ui = u0 / NU, uj0 = u0 - ui * NU;
    const int t = threadIdx.x;
    const int rowA = t >> 3;              // 0..15
    const int col  = (t & 7) * 4;         // float4 column

    const float* sb = som + (size_t)ui * IMG * SHAPE + uj0 * IMG;
    const float* vb = var + (size_t)ui * IMG * SHAPE + uj0 * IMG;

    const size_t oA = (size_t)rowA * SHAPE + col;
    const size_t oB = (size_t)(rowA + 16) * SHAPE + col;

    // 8 independent som/var loads batched up front (tiles 0 and 1)
    float4 sa0 = *(const float4*)(sb + oA);
    float4 sb0 = *(const float4*)(sb + oB);
    float4 sa1 = *(const float4*)(sb + oA + IMG);
    float4 sb1 = *(const float4*)(sb + oB + IMG);
    float4 va0 = *(const float4*)(vb + oA);
    float4 vb0 = *(const float4*)(vb + oB);
    float4 va1 = *(const float4*)(vb + oA + IMG);
    float4 vb1 = *(const float4*)(vb + oB + IMG);
    float4 x0 = *(const float4*)(x + rowA * IMG + col);
    float4 x1 = *(const float4*)(x + (rowA + 16) * IMG + col);

    float d;
    float acc0 = 0.0f, acc1 = 0.0f;
    d = sa0.x - x0.x; acc0 += __fdividef(d * d, va0.x);
    d = sa0.y - x0.y; acc0 += __fdividef(d * d, va0.y);
    d = sa0.z - x0.z; acc0 += __fdividef(d * d, va0.z);
    d = sa0.w - x0.w; acc0 += __fdividef(d * d, va0.w);
    d = sb0.x - x1.x; acc0 += __fdividef(d * d, vb0.x);
    d = sb0.y - x1.y; acc0 += __fdividef(d * d, vb0.y);
    d = sb0.z - x1.z; acc0 += __fdividef(d * d, vb0.z);
    d = sb0.w - x1.w; acc0 += __fdividef(d * d, vb0.w);
    d = sa1.x - x0.x; acc1 += __fdividef(d * d, va1.x);
    d = sa1.y - x0.y; acc1 += __fdividef(d * d, va1.y);
    d = sa1.z - x0.z; acc1 += __fdividef(d * d, va1.z);
    d = sa1.w - x0.w; acc1 += __fdividef(d * d, va1.w);
    d = sb1.x - x1.x; acc1 += __fdividef(d * d, vb1.x);
    d = sb1.y - x1.y; acc1 += __fdividef(d * d, vb1.y);
    d = sb1.z - x1.z; acc1 += __fdividef(d * d, vb1.z);
    d = sb1.w - x1.w; acc1 += __fdividef(d * d, vb1.w);

#pragma unroll
    for (int o = 16; o; o >>= 1) {
        acc0 += __shfl_down_sync(0xffffffffu, acc0, o);
        acc1 += __shfl_down_sync(0xffffffffu, acc1, o);
    }
    __shared__ float ws0[4], ws1[4];
    if ((t & 31) == 0) { ws0[t >> 5] = acc0; ws1[t >> 5] = acc1; }
    __syncthreads();
    if (t == 0) {
        g_z[u0]     = ws0[0] + ws0[1] + ws0[2] + ws0[3];
        g_z[u0 + 1] = ws1[0] + ws1[1] + ws1[2] + ws1[3];
    }

    // ---- last-block-done: global argmin + BMU scalars ----
    __shared__ bool amLast;
    if (t == 0) {
        __threadfence();
        unsigned old = atomicAdd(&g_count, 1u);
        amLast = (old == NBLK - 1);
    }
    __syncthreads();
    if (!amLast) return;
    __threadfence();

    unsigned long long best = 0xFFFFFFFFFFFFFFFFULL;
#pragma unroll
    for (int k = 0; k < NUNITS / 128; k++) {
        int e = t + k * 128;
        unsigned u = __float_as_uint(g_z[e]);
        u = (u & 0x80000000u) ? ~u : (u | 0x80000000u);   // orderable bits
        unsigned long long key = ((unsigned long long)u << 32) | (unsigned)e;
        best = min(best, key);
    }
#pragma unroll
    for (int o = 16; o; o >>= 1)
        best = min(best, __shfl_down_sync(0xffffffffu, best, o));
    __shared__ unsigned long long wm[4];
    if ((t & 31) == 0) wm[t >> 5] = best;
    __syncthreads();
    if (t == 0) {
        best = min(min(wm[0], wm[1]), min(wm[2], wm[3]));
        int bmu = (int)(best & 0xFFFFFFFFULL);
        float r   = radius[bmu];
        float lrb = lr[bmu];
        float dm  = 1.0f / (2.0f * r * r);
        g_params[0] = (float)(bmu / NU);
        g_params[1] = (float)(bmu % NU);
        g_params[2] = r;
        g_params[3] = dm;
        g_params[4] = -logf(1e-7f / lrb) / dm;
        g_bmu = bmu;
        g_count = 0;                        // reset for next graph replay
        __threadfence();
    }
}

// ---------------------------------------------------------------------------
// k_update: one 128-thread block per tile pair. 8 __ldlu reads batched,
// 8 __stcs streaming stores. Blocks 0..71 also emit radius/lr outputs.
// ---------------------------------------------------------------------------
__global__ void __launch_bounds__(128) k_update(const float* __restrict__ som,
                                                const float* __restrict__ var,
                                                const float* __restrict__ x,
                                                const float* __restrict__ lr,
                                                const float* __restrict__ radius,
                                                const float* __restrict__ bmu_count,
                                                float* __restrict__ out_som,
                                                float* __restrict__ out_var,
                                                float* __restrict__ out_rad,
                                                float* __restrict__ out_lr) {
    const int u0 = blockIdx.x * 2;
    const int ui = u0 / NU, uj0 = u0 - ui * NU;
    const int t = threadIdx.x;

    const float bi = g_params[0], bj = g_params[1];
    const float r = g_params[2], dm = g_params[3], cst = g_params[4];
    const int bmu = g_bmu;

    // Side job: radius / learning-rate outputs (blocks 0..71)
    if (blockIdx.x < NUNITS / 128) {
        int e = blockIdx.x * 128 + t;
        float c  = bmu_count[bmu * 10];
        float nr = expf(-c / 15.0f);
        float nl = expf(-c / 25.0f);
        out_rad[e] = fmaxf((e == bmu) ? nr : radius[e], 1e-5f);
        out_lr[e]  = fmaxf((e == bmu) ? nl : lr[e], 1e-5f);
    }

    const int rowA = t >> 3;
    const int col  = (t & 7) * 4;
    const size_t base = (size_t)ui * IMG * SHAPE + uj0 * IMG;
    const size_t oA = base + (size_t)rowA * SHAPE + col;
    const size_t oB = base + (size_t)(rowA + 16) * SHAPE + col;

    // 8 batched reads (L2-resident from k_z; last-use hint)
    float4 sa0 = __ldlu((const float4*)(som + oA));
    float4 sb0 = __ldlu((const float4*)(som + oB));
    float4 sa1 = __ldlu((const float4*)(som + oA + IMG));
    float4 sb1 = __ldlu((const float4*)(som + oB + IMG));
    float4 va0 = __ldlu((const float4*)(var + oA));
    float4 vb0 = __ldlu((const float4*)(var + oB));
    float4 va1 = __ldlu((const float4*)(var + oA + IMG));
    float4 vb1 = __ldlu((const float4*)(var + oB + IMG));
    float4 x0 = *(const float4*)(x + rowA * IMG + col);
    float4 x1 = *(const float4*)(x + (rowA + 16) * IMG + col);

    // Per-tile scalars (redundant per thread)
    const float di = (float)ui - bi;
    const float dj0 = (float)uj0 - bj;
    const float dj1 = (float)(uj0 + 1) - bj;
    float cart0 = sqrtf(di * di + dj0 * dj0);
    float cart1 = sqrtf(di * di + dj1 * dj1);
    float fm0 = lr[u0]     * expf(-((cart0 > r) ? 0.0f : cart0)) * dm;
    float fm1 = lr[u0 + 1] * expf(-((cart1 > r) ? 0.0f : cart1)) * dm;
    float vaA = fminf(fmaxf(0.4f + 1.0f / (1.0f + expf(-cart0 / cst)), 0.0f), 1.0f);
    float vaB = fminf(fmaxf(0.4f + 1.0f / (1.0f + expf(-cart1 / cst)), 0.0f), 1.0f);
    float ivA = 1.0f - vaA, ivB = 1.0f - vaB;

    float4 os, ov;
#define UPD1(S, X, V, FM, VA, IVA, OS, OV)                     \
    {                                                          \
        float ns = S + FM * (X - S);                           \
        float dd = X - ns;                                     \
        OV = VA * V + IVA * dd * dd;                           \
        OS = fminf(fmaxf(ns, 0.0f), 1.0f);                     \
    }
#define UPD4(SV, XV, VV, FM, VA, IVA, OUTS, OUTV, OFF)         \
    UPD1(SV.x, XV.x, VV.x, FM, VA, IVA, os.x, ov.x)            \
    UPD1(SV.y, XV.y, VV.y, FM, VA, IVA, os.y, ov.y)            \
    UPD1(SV.z, XV.z, VV.z, FM, VA, IVA, os.z, ov.z)            \
    UPD1(SV.w, XV.w, VV.w, FM, VA, IVA, os.w, ov.w)            \
    __stcs((float4*)(OUTS + OFF), os);                         \
    __stcs((float4*)(OUTV + OFF), ov);

    UPD4(sa0, x0, va0, fm0, vaA, ivA, out_som, out_var, oA)
    UPD4(sb0, x1, vb0, fm0, vaA, ivA, out_som, out_var, oB)
    UPD4(sa1, x0, va1, fm1, vaB, ivB, out_som, out_var, oA + IMG)
    UPD4(sb1, x1, vb1, fm1, vaB, ivB, out_som, out_var, oB + IMG)
#undef UPD4
#undef UPD1
}

extern "C" void kernel_launch(void* const* d_in, const int* in_sizes, int n_in,
                              void* d_out, int out_size) {
    const float* x      = (const float*)d_in[0];
    const float* som    = (const float*)d_in[1];
    const float* var    = (const float*)d_in[2];
    const float* radius = (const float*)d_in[3];
    const float* lr     = (const float*)d_in[4];
    const float* bmu    = (const float*)d_in[5];

    float* out      = (float*)d_out;
    float* out_som  = out;
    float* out_var  = out + (size_t)NELEM;
    float* out_rad  = out + 2ULL * NELEM;
    float* out_lr   = out + 2ULL * NELEM + NUNITS;

    k_z<<<NBLK, 128>>>(som, var, x, radius, lr);
    k_update<<<NBLK, 128>>>(som, var, x, lr, radius, bmu,
                            out_som, out_var, out_rad, out_lr);
}